// round 14
// baseline (speedup 1.0000x reference)
#include <cuda_runtime.h>
#include <cuda_fp16.h>
#include <math.h>

#define N_NODES  1000000
#define N_EDGES  16000000
#define N_GRAPHS 1024

// ---------------- scratch (device globals: allocation-free) ----------------
__device__ __align__(16) uint4    g_y1h[N_NODES];       // y1 = f@W1 (no norm): 1M x 8 fp16
__device__ __align__(16) uint4    g_x1h[N_NODES];       // x1 = y1*onorm: 1M x 8 fp16
__device__ __align__(16) uint2    g_x2h[N_NODES];       // x2: 1M x 4 fp16
__device__ __align__(16) unsigned g_agg1[N_NODES * 4];  // agg1: 1M x 8 fp16
__device__ __align__(16) unsigned g_agg2[N_NODES * 2];  // agg2: 1M x 4 fp16
__device__ __align__(16) int      g_deg_out[N_NODES];
__device__ __align__(16) int      g_deg_in[N_NODES];
__device__ float g_gsum[N_GRAPHS * 4];
__device__ float g_gcnt[N_GRAPHS];

__device__ __forceinline__ unsigned pack_h2(float x, float y) {
    __half2 h = __float22half2_rn(make_float2(x, y));
    return *reinterpret_cast<unsigned*>(&h);
}
__device__ __forceinline__ float2 unpack_h2(unsigned u) {
    __half2 h = *reinterpret_cast<__half2*>(&u);
    return __half22float2(h);
}
__device__ __forceinline__ unsigned mul_h2(unsigned u, __half2 s) {
    __half2 h = *reinterpret_cast<__half2*>(&u);
    h = __hmul2(h, s);
    return *reinterpret_cast<unsigned*>(&h);
}

__device__ __forceinline__ void red_add_v4h2(unsigned* p, uint4 v) {
    asm volatile("red.global.add.noftz.v4.f16x2 [%0], {%1,%2,%3,%4};"
                 :: "l"(p), "r"(v.x), "r"(v.y), "r"(v.z), "r"(v.w) : "memory");
}
__device__ __forceinline__ void red_add_v2h2(unsigned* p, uint2 v) {
    asm volatile("red.global.add.noftz.v2.f16x2 [%0], {%1,%2};"
                 :: "l"(p), "r"(v.x), "r"(v.y) : "memory");
}

__device__ __forceinline__ void pdl_begin() {
    cudaTriggerProgrammaticLaunchCompletion();
    cudaGridDependencySynchronize();
}

// ---------------- kernels ----------------

// main-chain head: zero the two degree arrays (needed before deg_out/scatter1)
__global__ void k_zero() {
    pdl_begin();
    int i = blockIdx.x * blockDim.x + threadIdx.x;
    if (i < N_NODES / 4) { ((int4*)g_deg_out)[i] = make_int4(0, 0, 0, 0);
                           ((int4*)g_deg_in)[i]  = make_int4(0, 0, 0, 0); }
}

// out-degrees: 8 edges per thread
__global__ void k_deg_out(const int* __restrict__ src) {
    pdl_begin();
    int i = blockIdx.x * blockDim.x + threadIdx.x;
    if (i >= N_EDGES / 8) return;
    int4 s0 = ((const int4*)src)[2 * i], s1 = ((const int4*)src)[2 * i + 1];
    atomicAdd(&g_deg_out[s0.x], 1); atomicAdd(&g_deg_out[s0.y], 1);
    atomicAdd(&g_deg_out[s0.z], 1); atomicAdd(&g_deg_out[s0.w], 1);
    atomicAdd(&g_deg_out[s1.x], 1); atomicAdd(&g_deg_out[s1.y], 1);
    atomicAdd(&g_deg_out[s1.z], 1); atomicAdd(&g_deg_out[s1.w], 1);
}

// SIDE STREAM: y1 = f @ W1 (no norm, no degrees needed) + zero agg1/agg2/graph
// accumulators (all consumed only after the side-stream join before scatter1).
__global__ void k_proj1a(const float* __restrict__ feat, const float* __restrict__ W1) {
    __shared__ float sW[80];
    if (threadIdx.x < 80) sW[threadIdx.x] = W1[threadIdx.x];
    __syncthreads();
    int n = blockIdx.x * blockDim.x + threadIdx.x;
    if (n >= N_NODES) return;
    ((uint4*)g_agg1)[n] = make_uint4(0u, 0u, 0u, 0u);
    ((uint2*)g_agg2)[n] = make_uint2(0u, 0u);
    if (n < N_GRAPHS) { ((float4*)g_gsum)[n] = make_float4(0.f,0.f,0.f,0.f);
                        g_gcnt[n] = 0.f; }
    const float2* fp = (const float2*)(feat + (size_t)n * 10);
    float f[10];
#pragma unroll
    for (int i = 0; i < 5; i++) { float2 v = fp[i]; f[2*i] = v.x; f[2*i+1] = v.y; }
    float o[8];
#pragma unroll
    for (int j = 0; j < 8; j++) o[j] = 0.f;
#pragma unroll
    for (int i = 0; i < 10; i++)
#pragma unroll
        for (int j = 0; j < 8; j++) o[j] += f[i] * sW[i * 8 + j];
    g_y1h[n] = make_uint4(pack_h2(o[0], o[1]), pack_h2(o[2], o[3]),
                          pack_h2(o[4], o[5]), pack_h2(o[6], o[7]));
}

// x1 = y1 * out_norm (half2 multiplies)
__global__ void k_proj1b() {
    pdl_begin();
    int n = blockIdx.x * blockDim.x + threadIdx.x;
    if (n >= N_NODES) return;
    float onf = rsqrtf(fmaxf((float)g_deg_out[n], 1.f));
    __half2 on = __float2half2_rn(onf);
    uint4 y = g_y1h[n];
    g_x1h[n] = make_uint4(mul_h2(y.x, on), mul_h2(y.y, on),
                          mul_h2(y.z, on), mul_h2(y.w, on));
}

// agg1[dst] += x1h[src]; also accumulates deg_in (dst already in registers)
__global__ void k_scatter1(const int* __restrict__ src, const int* __restrict__ dst) {
    pdl_begin();
    int i = blockIdx.x * blockDim.x + threadIdx.x;   // exact grid: N_EDGES/4
    int4 s = ((const int4*)src)[i];
    int4 d = ((const int4*)dst)[i];
    uint4 v0 = __ldg(&g_x1h[s.x]);
    uint4 v1 = __ldg(&g_x1h[s.y]);
    uint4 v2 = __ldg(&g_x1h[s.z]);
    uint4 v3 = __ldg(&g_x1h[s.w]);
    red_add_v4h2(&g_agg1[(size_t)d.x * 4], v0);
    red_add_v4h2(&g_agg1[(size_t)d.y * 4], v1);
    red_add_v4h2(&g_agg1[(size_t)d.z * 4], v2);
    red_add_v4h2(&g_agg1[(size_t)d.w * 4], v3);
    atomicAdd(&g_deg_in[d.x], 1);
    atomicAdd(&g_deg_in[d.y], 1);
    atomicAdd(&g_deg_in[d.z], 1);
    atomicAdd(&g_deg_in[d.w], 1);
}

// h1 = relu(fp32(agg1)*in_norm + b1); x2 = (h1*out_norm) @ W2 fp16-packed
__global__ void k_h1_proj2(const float* __restrict__ W2, const float* __restrict__ b1) {
    pdl_begin();
    __shared__ float sW[32], sb[8];
    if (threadIdx.x < 32) sW[threadIdx.x] = W2[threadIdx.x];
    if (threadIdx.x < 8)  sb[threadIdx.x] = b1[threadIdx.x];
    __syncthreads();
    int n = blockIdx.x * blockDim.x + threadIdx.x;
    if (n >= N_NODES) return;
    float innorm = rsqrtf(fmaxf((float)g_deg_in[n], 1.f));
    float onorm  = rsqrtf(fmaxf((float)g_deg_out[n], 1.f));
    uint4 raw = ((const uint4*)g_agg1)[n];
    float2 p0 = unpack_h2(raw.x), p1 = unpack_h2(raw.y);
    float2 p2 = unpack_h2(raw.z), p3 = unpack_h2(raw.w);
    float h[8] = { p0.x, p0.y, p1.x, p1.y, p2.x, p2.y, p3.x, p3.y };
#pragma unroll
    for (int j = 0; j < 8; j++) h[j] = fmaxf(h[j] * innorm + sb[j], 0.f);
    float o[4] = {0.f, 0.f, 0.f, 0.f};
#pragma unroll
    for (int j = 0; j < 8; j++)
#pragma unroll
        for (int k = 0; k < 4; k++) o[k] += h[j] * sW[j * 4 + k];
    g_x2h[n] = make_uint2(pack_h2(o[0] * onorm, o[1] * onorm),
                          pack_h2(o[2] * onorm, o[3] * onorm));
}

// agg2[dst] += x2h[src]  -- 4 edges/thread
__global__ void k_scatter2(const int* __restrict__ src, const int* __restrict__ dst) {
    pdl_begin();
    int i = blockIdx.x * blockDim.x + threadIdx.x;   // exact grid: N_EDGES/4
    int4 s = ((const int4*)src)[i];
    int4 d = ((const int4*)dst)[i];
    uint2 v0 = __ldg(&g_x2h[s.x]);
    uint2 v1 = __ldg(&g_x2h[s.y]);
    uint2 v2 = __ldg(&g_x2h[s.z]);
    uint2 v3 = __ldg(&g_x2h[s.w]);
    red_add_v2h2(&g_agg2[(size_t)d.x * 2], v0);
    red_add_v2h2(&g_agg2[(size_t)d.y * 2], v1);
    red_add_v2h2(&g_agg2[(size_t)d.z * 2], v2);
    red_add_v2h2(&g_agg2[(size_t)d.w * 2], v3);
}

// h2 = relu(fp32(agg2) * in_norm + b2); per-graph mean accumulation
__global__ void k_graph_reduce(const int* __restrict__ graph_ids, const float* __restrict__ b2) {
    pdl_begin();
    int n0 = blockIdx.x * blockDim.x + threadIdx.x;
    bool valid = (n0 < N_NODES);
    int n = valid ? n0 : (N_NODES - 1);
    uint2 raw = ((const uint2*)g_agg2)[n];
    float2 p0 = unpack_h2(raw.x), p1 = unpack_h2(raw.y);
    float innorm = rsqrtf(fmaxf((float)g_deg_in[n], 1.f));
    float h[4];
    h[0] = valid ? fmaxf(p0.x * innorm + __ldg(b2 + 0), 0.f) : 0.f;
    h[1] = valid ? fmaxf(p0.y * innorm + __ldg(b2 + 1), 0.f) : 0.f;
    h[2] = valid ? fmaxf(p1.x * innorm + __ldg(b2 + 2), 0.f) : 0.f;
    h[3] = valid ? fmaxf(p1.y * innorm + __ldg(b2 + 3), 0.f) : 0.f;
    float cnt = valid ? 1.f : 0.f;
    int gid = __ldg(graph_ids + n);

    unsigned full = 0xFFFFFFFFu;
    int g0 = __shfl_sync(full, gid, 0);
    bool uniform = __all_sync(full, gid == g0);
    int lane = threadIdx.x & 31;
    if (uniform) {
#pragma unroll
        for (int off = 16; off > 0; off >>= 1) {
#pragma unroll
            for (int k = 0; k < 4; k++) h[k] += __shfl_down_sync(full, h[k], off);
            cnt += __shfl_down_sync(full, cnt, off);
        }
        if (lane == 0) {
#pragma unroll
            for (int k = 0; k < 4; k++) atomicAdd(&g_gsum[g0 * 4 + k], h[k]);
            atomicAdd(&g_gcnt[g0], cnt);
        }
    } else if (valid) {
#pragma unroll
        for (int k = 0; k < 4; k++) atomicAdd(&g_gsum[gid * 4 + k], h[k]);
        atomicAdd(&g_gcnt[gid], 1.f);
    }
}

// out[g] = sigmoid(mean @ Wo + bo)
__global__ void k_final(const float* __restrict__ Wo, const float* __restrict__ bo,
                        float* __restrict__ out) {
    pdl_begin();
    int g = blockIdx.x * blockDim.x + threadIdx.x;
    if (g >= N_GRAPHS) return;
    float c = fmaxf(g_gcnt[g], 1.f);
    float z = __ldg(bo);
#pragma unroll
    for (int k = 0; k < 4; k++) z += (g_gsum[g * 4 + k] / c) * __ldg(Wo + k);
    out[g] = 1.f / (1.f + expf(-z));
}

// ---------------- launch ----------------
template <typename... Args>
static void launch_pdl(void (*kern)(Args...), int grid, int block, Args... args) {
    cudaLaunchConfig_t cfg = {};
    cfg.gridDim = dim3(grid, 1, 1);
    cfg.blockDim = dim3(block, 1, 1);
    cfg.stream = 0;
    cudaLaunchAttribute attr[1];
    attr[0].id = cudaLaunchAttributeProgrammaticStreamSerialization;
    attr[0].val.programmaticStreamSerializationAllowed = 1;
    cfg.attrs = attr;
    cfg.numAttrs = 1;
    cudaLaunchKernelEx(&cfg, kern, args...);
}

extern "C" void kernel_launch(void* const* d_in, const int* in_sizes, int n_in,
                              void* d_out, int out_size) {
    const float* feat      = (const float*)d_in[0];
    const int*   src       = (const int*)d_in[1];
    const int*   dst       = (const int*)d_in[2];
    const int*   graph_ids = (const int*)d_in[3];
    const float* W1        = (const float*)d_in[4];
    const float* b1        = (const float*)d_in[5];
    const float* W2        = (const float*)d_in[6];
    const float* b2        = (const float*)d_in[7];
    const float* Wo        = (const float*)d_in[8];
    const float* bo        = (const float*)d_in[9];
    float* out = (float*)d_out;

    cudaStream_t s2;
    cudaStreamCreateWithFlags(&s2, cudaStreamNonBlocking);
    cudaEvent_t evFork, evJoin;
    cudaEventCreateWithFlags(&evFork, cudaEventDisableTiming);
    cudaEventCreateWithFlags(&evJoin, cudaEventDisableTiming);

    const int T = 256;
    const int gN = (N_NODES + T - 1) / T;

    // side stream: DRAM-bound GEMM + all aggregator zeroing (overlaps deg_out)
    cudaEventRecord(evFork, 0);
    cudaStreamWaitEvent(s2, evFork, 0);
    k_proj1a<<<gN, T, 0, s2>>>(feat, W1);
    cudaEventRecord(evJoin, s2);

    // main chain: L2-op-bound work
    launch_pdl(k_zero, (N_NODES / 4 + T - 1) / T, T);
    launch_pdl(k_deg_out, (N_EDGES / 8 + T - 1) / T, T, src);
    cudaStreamWaitEvent(0, evJoin, 0);
    launch_pdl(k_proj1b, gN, T);
    launch_pdl(k_scatter1, (N_EDGES / 4) / T, T, src, dst);
    launch_pdl(k_h1_proj2, gN, T, W2, b1);
    launch_pdl(k_scatter2, (N_EDGES / 4) / T, T, src, dst);
    launch_pdl(k_graph_reduce, gN, T, graph_ids, b2);
    launch_pdl(k_final, (N_GRAPHS + T - 1) / T, T, Wo, bo, out);
}